// round 8
// baseline (speedup 1.0000x reference)
#include <cuda_runtime.h>
#include <cstdint>

// Model_39676907886975: fused attention, fp32, shapes (256,32,16,64).
//   attn = softmax(q @ k^T / sqrt(8) + 1), dropout(p=0.3, JAX partitionable
//   threefry key=(0,42)), out = attn @ v.
// R7: warp = 2 bh (32-thr CTA), 4x4 logit register tiles (strided quads),
// inline per-lane threefry, p stored once as s-quads, V read from global L1
// (prefetched), all-warp sync only.

#define ROTL32(x, r) (((x) << (r)) | ((x) >> (32 - (r))))

__device__ __forceinline__ uint32_t tf_bits_0_42(uint32_t idx) {
    // JAX partitionable threefry: (o0,o1) = threefry2x32((0,42),(0,idx)); o0^o1
    uint32_t x0 = 0u, x1 = idx;
    const uint32_t ks0 = 0u;
    const uint32_t ks1 = 42u;
    const uint32_t ks2 = 0x1BD11BDAu ^ ks0 ^ ks1;
    x0 += ks0; x1 += ks1;
#define TF_R4(a, b, c, d)                       \
    x0 += x1; x1 = ROTL32(x1, a); x1 ^= x0;     \
    x0 += x1; x1 = ROTL32(x1, b); x1 ^= x0;     \
    x0 += x1; x1 = ROTL32(x1, c); x1 ^= x0;     \
    x0 += x1; x1 = ROTL32(x1, d); x1 ^= x0;
    TF_R4(13, 15, 26, 6)   x0 += ks1; x1 += ks2 + 1u;
    TF_R4(17, 29, 16, 24)  x0 += ks2; x1 += ks0 + 2u;
    TF_R4(13, 15, 26, 6)   x0 += ks0; x1 += ks1 + 3u;
    TF_R4(17, 29, 16, 24)  x0 += ks1; x1 += ks2 + 4u;
    TF_R4(13, 15, 26, 6)   x0 += ks2; x1 += ks0 + 5u;
#undef TF_R4
    return x0 ^ x1;
}

__device__ __forceinline__ float drop_scale(uint32_t idx) {
    uint32_t bits = tf_bits_0_42(idx);
    float u = __uint_as_float((bits >> 9) | 0x3F800000u) - 1.0f;
    return (u < 0.7f) ? (1.0f / 0.7f) : 0.0f;
}

// ---- packed fp32x2 helpers ----
__device__ __forceinline__ unsigned long long fma2(
    unsigned long long a, unsigned long long b, unsigned long long c) {
    unsigned long long d;
    asm("fma.rn.f32x2 %0, %1, %2, %3;" : "=l"(d) : "l"(a), "l"(b), "l"(c));
    return d;
}
__device__ __forceinline__ unsigned long long pack2dup(float x) {
    unsigned long long r;
    asm("mov.b64 %0, {%1, %1};" : "=l"(r) : "f"(x));
    return r;
}
__device__ __forceinline__ float hadd2(unsigned long long a) {
    float lo, hi;
    asm("mov.b64 {%0, %1}, %2;" : "=f"(lo), "=f"(hi) : "l"(a));
    return lo + hi;
}

struct BHS {
    float4 qs[16][17];   // 17-f4 row stride: contiguous-row gathers conflict-free
    float4 ks[16][17];
    float4 ps4[16][4];   // ps4[t][sq] = (p[sq][t], p[sq+4][t], p[sq+8][t], p[sq+12][t])
    float4 pad[4];       // sizeof(BHS) % 128 == 64: bank-staggers the two bh halves
};

__global__ __launch_bounds__(32) void attn_fused_kernel(
    const float* __restrict__ q,
    const float* __restrict__ k,
    const float* __restrict__ v,
    float* __restrict__ out)
{
    __shared__ BHS sh[2];

    const int lane = threadIdx.x;
    const int hf   = lane >> 4;     // which bh of the pair this lane handles (logits)
    const int c16  = lane & 15;
    const int sg   = c16 >> 2;      // 0..3 -> s rows {sg, sg+4, sg+8, sg+12}
    const int tg   = c16 & 3;       // 0..3 -> t cols {tg, tg+4, tg+8, tg+12}
    const int bh0  = blockIdx.x * 2;

    // ---- stage q,k for both bh (coalesced LDG.128); prefetch v into L1 ----
#pragma unroll
    for (int g = 0; g < 2; ++g) {
        const float4* q4 = reinterpret_cast<const float4*>(q) + (size_t)(bh0 + g) * 256;
        const float4* k4 = reinterpret_cast<const float4*>(k) + (size_t)(bh0 + g) * 256;
#pragma unroll
        for (int m = 0; m < 8; ++m) {
            int idx = lane + 32 * m;
            int r = idx >> 4, c = idx & 15;
            sh[g].qs[r][c] = q4[idx];
            sh[g].ks[r][c] = k4[idx];
        }
        const char* vp = reinterpret_cast<const char*>(
            reinterpret_cast<const float4*>(v) + (size_t)(bh0 + g) * 256) + lane * 128;
        asm volatile("prefetch.global.L1 [%0];" :: "l"(vp));
    }
    __syncwarp();

    // ---- logits: 4x4 block per lane (lanes 0-15 -> bh0, 16-31 -> bh0+1) ----
    BHS& S = sh[hf];
    unsigned long long acc[4][4];
#pragma unroll
    for (int j = 0; j < 4; ++j)
#pragma unroll
        for (int jb = 0; jb < 4; ++jb) acc[j][jb] = 0ull;

#pragma unroll
    for (int i = 0; i < 16; ++i) {
        ulonglong2 A[4], B[4];
#pragma unroll
        for (int j = 0; j < 4; ++j)
            A[j] = *reinterpret_cast<const ulonglong2*>(&S.qs[sg + 4 * j][i]);
#pragma unroll
        for (int j = 0; j < 4; ++j)
            B[j] = *reinterpret_cast<const ulonglong2*>(&S.ks[tg + 4 * j][i]);
#pragma unroll
        for (int j = 0; j < 4; ++j)
#pragma unroll
            for (int jb = 0; jb < 4; ++jb) {
                acc[j][jb] = fma2(A[j].x, B[jb].x, acc[j][jb]);
                acc[j][jb] = fma2(A[j].y, B[jb].y, acc[j][jb]);
            }
    }

    const float SCALE = 0.35355339059327373f;   // 1/sqrt(8)
    float e[4][4], inv[4];
#pragma unroll
    for (int j = 0; j < 4; ++j) {
        float part = 0.0f;
#pragma unroll
        for (int jb = 0; jb < 4; ++jb) {
            // no max-subtraction: |logit| <~ 20 for N(0,1) inputs, safe in fp32
            e[j][jb] = __expf(fmaf(hadd2(acc[j][jb]), SCALE, 1.0f));
            part += e[j][jb];
        }
        // row sum across the 4 tg lanes (lanes xor 1,2 stay inside the quad)
        part += __shfl_xor_sync(0xFFFFFFFFu, part, 1);
        part += __shfl_xor_sync(0xFFFFFFFFu, part, 2);
        inv[j] = __fdividef(1.0f, part);
    }

    // ---- p = softmax * dropout (inline threefry), write s-quads ----
    const uint32_t ibase = (uint32_t)(bh0 + hf) * 256u;
#pragma unroll
    for (int jb = 0; jb < 4; ++jb) {
        const int t = tg + 4 * jb;
        float4 quad;
        quad.x = e[0][jb] * inv[0] * drop_scale(ibase + (sg +  0) * 16 + t);
        quad.y = e[1][jb] * inv[1] * drop_scale(ibase + (sg +  4) * 16 + t);
        quad.z = e[2][jb] * inv[2] * drop_scale(ibase + (sg +  8) * 16 + t);
        quad.w = e[3][jb] * inv[3] * drop_scale(ibase + (sg + 12) * 16 + t);
        S.ps4[t][sg] = quad;
    }
    __syncwarp();

    // ---- PV: full warp per bh; lane = (sq, cb); rows {sq+4j}, chunks {cb, cb+8} ----
    const int sq = lane >> 3;      // 0..3
    const int cb = lane & 7;       // 0..7
#pragma unroll
    for (int g = 0; g < 2; ++g) {
        const float4* v4 = reinterpret_cast<const float4*>(v) + (size_t)(bh0 + g) * 256;
        float4*       o4 = reinterpret_cast<float4*>(out)    + (size_t)(bh0 + g) * 256;

        unsigned long long o[4][2][2];
#pragma unroll
        for (int j = 0; j < 4; ++j)
#pragma unroll
            for (int h = 0; h < 2; ++h) { o[j][h][0] = 0ull; o[j][h][1] = 0ull; }

#pragma unroll
        for (int t = 0; t < 16; ++t) {
            float4 wq = sh[g].ps4[t][sq];
            unsigned long long w[4] = { pack2dup(wq.x), pack2dup(wq.y),
                                        pack2dup(wq.z), pack2dup(wq.w) };
            ulonglong2 V0 = *reinterpret_cast<const ulonglong2*>(&v4[t * 16 + cb]);
            ulonglong2 V1 = *reinterpret_cast<const ulonglong2*>(&v4[t * 16 + cb + 8]);
#pragma unroll
            for (int j = 0; j < 4; ++j) {
                o[j][0][0] = fma2(w[j], V0.x, o[j][0][0]);
                o[j][0][1] = fma2(w[j], V0.y, o[j][0][1]);
                o[j][1][0] = fma2(w[j], V1.x, o[j][1][0]);
                o[j][1][1] = fma2(w[j], V1.y, o[j][1][1]);
            }
        }

#pragma unroll
        for (int j = 0; j < 4; ++j) {
#pragma unroll
            for (int h = 0; h < 2; ++h) {
                *reinterpret_cast<ulonglong2*>(&o4[(sq + 4 * j) * 16 + cb + 8 * h]) =
                    make_ulonglong2(o[j][h][0], o[j][h][1]);
            }
        }
    }
}

extern "C" void kernel_launch(void* const* d_in, const int* in_sizes, int n_in,
                              void* d_out, int out_size)
{
    const float* q = (const float*)d_in[0];
    const float* k = (const float*)d_in[1];
    const float* v = (const float*)d_in[2];
    float* out = (float*)d_out;
    // 8192 bh total, 2 bh per 32-thread CTA
    attn_fused_kernel<<<4096, 32>>>(q, k, v, out);
}